// round 1
// baseline (speedup 1.0000x reference)
#include <cuda_runtime.h>
#include <cstdint>
#include <math.h>

#define IMG_H 128
#define IMG_W 128
#define HW (IMG_H * IMG_W)
#define B_MAX 4
#define N_MAX 4096
#define EPSF 1e-9f

// Scratch (allocation-free: __device__ globals)
__device__ float4 g_verts[B_MAX * N_MAX];                 // (sx, sy, sz, w) per vertex per batch
__device__ unsigned long long g_zbuf[B_MAX * HW];         // (ordered_z << 32) | face_id

// ---------------------------------------------------------------------------
// Kernel 1: clear z-buffer
// ---------------------------------------------------------------------------
__global__ void k_init(int total) {
    int i = blockIdx.x * blockDim.x + threadIdx.x;
    if (i < total) g_zbuf[i] = 0xFFFFFFFFFFFFFFFFull;
}

// ---------------------------------------------------------------------------
// Kernel 2: vertex transform -> screen coords + clip w
// One block per batch; every thread builds the (tiny) matrices redundantly.
// ---------------------------------------------------------------------------
__global__ void k_transform(const float* __restrict__ vertices,
                            const float* __restrict__ poses,
                            int N) {
    int b = blockIdx.x;
    const float* P = poses + b * 16;

    // cam_pose C: rows 0..2 of rot scaled by G = diag(1,-1,-1); t_y,t_z negated
    float C[4][4];
    const float sgn[3] = {1.f, -1.f, -1.f};
#pragma unroll
    for (int r = 0; r < 3; ++r)
#pragma unroll
        for (int c = 0; c < 3; ++c)
            C[r][c] = sgn[r] * P[r * 4 + c];
    C[0][3] = P[3];
    C[1][3] = -P[7];
    C[2][3] = -P[11];
#pragma unroll
    for (int c = 0; c < 4; ++c) C[3][c] = P[12 + c];

    // Projection constants (computed in double, stored f32 — matches numpy)
    const double NEAR = 0.1, FAR = 10.0, FOCAL = 140.0;
    const double RIGHT = (IMG_W - 1.0) / 2.0 * NEAR / FOCAL;
    const double TOP = RIGHT * ((double)IMG_H / (double)IMG_W);
    const float p00 = (float)(NEAR / RIGHT);
    const float p11 = (float)(NEAR / TOP);
    const float p22 = (float)(-(FAR + NEAR) / (FAR - NEAR));
    const float p32 = (float)(-2.0 * FAR * NEAR / (FAR - NEAR));

    const float* vb = vertices + (size_t)b * N * 3;
    for (int v = threadIdx.x; v < N; v += blockDim.x) {
        float x = vb[v * 3 + 0], y = vb[v * 3 + 1], z = vb[v * 3 + 2];
        // view-space: v4_k = x*C[k][0] + y*C[k][1] + z*C[k][2] + C[k][3]
        float v0 = x * C[0][0] + y * C[0][1] + z * C[0][2] + C[0][3];
        float v1 = x * C[1][0] + y * C[1][1] + z * C[1][2] + C[1][3];
        float v2 = x * C[2][0] + y * C[2][1] + z * C[2][2] + C[2][3];
        float v3 = x * C[3][0] + y * C[3][1] + z * C[3][2] + C[3][3];
        // clip = v4 @ PROJ (PROJ is sparse)
        float cx = v0 * p00;
        float cy = v1 * p11;
        float cz = v2 * p22 + v3 * p32;
        float cw = -v2;
        float sx = (cx / cw * 0.5f + 0.5f) * (float)IMG_W;
        float sy = (0.5f - cy / cw * 0.5f) * (float)IMG_H;
        float sz = cz / cw;
        g_verts[b * N + v] = make_float4(sx, sy, sz, cw);
    }
}

// ---------------------------------------------------------------------------
// Kernel 3: warp-per-face rasterization with 64-bit atomicMin depth buffer.
// Key = (ordered_float(z) << 32) | face_id  -> lexicographic (z, fid) min,
// which is exactly the reference's chunked-argmin tie-breaking.
// ---------------------------------------------------------------------------
__global__ void k_raster(const int* __restrict__ faces, int N, int F, int B) {
    int gw = (blockIdx.x * blockDim.x + threadIdx.x) >> 5;
    int lane = threadIdx.x & 31;
    if (gw >= B * F) return;
    int b = gw / F;
    int f = gw - b * F;

    int i0 = faces[3 * f + 0];
    int i1 = faces[3 * f + 1];
    int i2 = faces[3 * f + 2];
    float4 v0 = g_verts[b * N + i0];
    float4 v1 = g_verts[b * N + i1];
    float4 v2 = g_verts[b * N + i2];

    if (!(v0.w > 1e-6f && v1.w > 1e-6f && v2.w > 1e-6f)) return;

    float minx = fminf(v0.x, fminf(v1.x, v2.x));
    float maxx = fmaxf(v0.x, fmaxf(v1.x, v2.x));
    float miny = fminf(v0.y, fminf(v1.y, v2.y));
    float maxy = fmaxf(v0.y, fmaxf(v1.y, v2.y));

    // widen by a pixel to absorb fp rounding of the edge functions
    int c0 = max(0, (int)floorf(minx - 0.5f));
    int c1 = min(IMG_W - 1, (int)ceilf(maxx - 0.5f));
    int r0 = max(0, (int)floorf(miny - 0.5f));
    int r1 = min(IMG_H - 1, (int)ceilf(maxy - 0.5f));
    if (c1 < c0 || r1 < r0) return;

    float x0 = v0.x, y0 = v0.y, x1 = v1.x, y1 = v1.y, x2 = v2.x, y2 = v2.y;
    float dx0 = x2 - x1, dy0 = y2 - y1;
    float dx1 = x0 - x2, dy1 = y0 - y2;
    float dx2 = x1 - x0, dy2 = y1 - y0;
    float z0 = v0.z, z1 = v1.z, z2 = v2.z;

    unsigned long long* zb = g_zbuf + b * HW;
    unsigned int fid = (unsigned int)f;

    for (int r = r0; r <= r1; ++r) {
        float py = (float)r + 0.5f;
        for (int c = c0 + lane; c <= c1; c += 32) {
            float px = (float)c + 0.5f;
            float e0 = dx0 * (py - y1) - dy0 * (px - x1);
            float e1 = dx1 * (py - y2) - dy1 * (px - x2);
            float e2 = dx2 * (py - y0) - dy2 * (px - x0);
            float area = (e0 + e1) + e2;
            if (fabsf(area) <= EPSF) continue;
            float s = area > 0.f ? 1.f : -1.f;
            if (e0 * s < 0.f || e1 * s < 0.f || e2 * s < 0.f) continue;
            float z = (e0 * z0 + e1 * z1 + e2 * z2) / area;
            if (!(z >= -1.f && z <= 1.f)) continue;
            unsigned int uz = __float_as_uint(z);
            uz = (uz & 0x80000000u) ? ~uz : (uz | 0x80000000u);
            unsigned long long key = ((unsigned long long)uz << 32) | fid;
            atomicMin(zb + r * IMG_W + c, key);
        }
    }
}

// ---------------------------------------------------------------------------
// Kernel 4: per-pixel perspective-correct shade + bilinear texture sample
// ---------------------------------------------------------------------------
__global__ void k_shade(const float* __restrict__ uv_map,
                        const int* __restrict__ faces,
                        const float* __restrict__ texture,
                        float* __restrict__ out,
                        int N, int F, int TH, int TW, int B) {
    int p = blockIdx.x * blockDim.x + threadIdx.x;
    if (p >= B * HW) return;
    int b = p / HW;
    int rc = p - b * HW;
    int r = rc / IMG_W;
    int c = rc - r * IMG_W;

    float o0 = 0.f, o1 = 0.f, o2 = 0.f;
    unsigned long long key = g_zbuf[p];
    if (key != 0xFFFFFFFFFFFFFFFFull) {
        int f = (int)(unsigned int)(key & 0xFFFFFFFFull);
        int i0 = faces[3 * f + 0];
        int i1 = faces[3 * f + 1];
        int i2 = faces[3 * f + 2];
        float4 v0 = g_verts[b * N + i0];
        float4 v1 = g_verts[b * N + i1];
        float4 v2 = g_verts[b * N + i2];

        float px = (float)c + 0.5f, py = (float)r + 0.5f;
        float e0 = (v2.x - v1.x) * (py - v1.y) - (v2.y - v1.y) * (px - v1.x);
        float e1 = (v0.x - v2.x) * (py - v2.y) - (v0.y - v2.y) * (px - v2.x);
        float e2 = (v1.x - v0.x) * (py - v0.y) - (v1.y - v0.y) * (px - v0.x);

        float bw0 = e0 / v0.w, bw1 = e1 / v1.w, bw2 = e2 / v2.w;
        float denom = (bw0 + bw1) + bw2;
        if (fabsf(denom) <= EPSF) denom = 1.f;
        float pc0 = bw0 / denom, pc1 = bw1 / denom, pc2 = bw2 / denom;

        float mask = (pc0 + pc1) + pc2;  // col channel 0 is all-ones

        const float* uvb = uv_map + (size_t)b * N * 2;
        float u = pc0 * uvb[i0 * 2 + 0] + pc1 * uvb[i1 * 2 + 0] + pc2 * uvb[i2 * 2 + 0];
        float v = pc0 * uvb[i0 * 2 + 1] + pc1 * uvb[i1 * 2 + 1] + pc2 * uvb[i2 * 2 + 1];

        // sample_texture: idx = clip(uv reversed) * (th, tw)
        float fyf = fminf(fmaxf(v, 0.f), 1.f) * (float)TH;
        float fxf = fminf(fmaxf(u, 0.f), 1.f) * (float)TW;
        float fly = floorf(fyf), flx = floorf(fxf);
        float fry = fyf - fly, frx = fxf - flx;
        int iy = (int)fly, ix = (int)flx;
        int iy0 = min(max(iy, 0), TH - 1);
        int iy1 = min(max(iy + 1, 0), TH - 1);
        int ix0 = min(max(ix, 0), TW - 1);
        int ix1 = min(max(ix + 1, 0), TW - 1);

        const float* T = texture + (size_t)b * TH * TW * 3;
        const float* tl = T + ((size_t)iy0 * TW + ix0) * 3;
        const float* tr = T + ((size_t)iy0 * TW + ix1) * 3;
        const float* bl = T + ((size_t)iy1 * TW + ix0) * 3;
        const float* br = T + ((size_t)iy1 * TW + ix1) * 3;

        float wtl = (1.f - frx) * (1.f - fry);
        float wtr = frx * (1.f - fry);
        float wbl = (1.f - frx) * fry;
        float wbr = frx * fry;

        o0 = (tl[0] * wtl + tr[0] * wtr + bl[0] * wbl + br[0] * wbr) * mask;
        o1 = (tl[1] * wtl + tr[1] * wtr + bl[1] * wbl + br[1] * wbr) * mask;
        o2 = (tl[2] * wtl + tr[2] * wtr + bl[2] * wbl + br[2] * wbr) * mask;
    }
    float* op = out + (size_t)p * 3;
    op[0] = o0;
    op[1] = o1;
    op[2] = o2;
}

// ---------------------------------------------------------------------------
// Launch
// ---------------------------------------------------------------------------
extern "C" void kernel_launch(void* const* d_in, const int* in_sizes, int n_in,
                              void* d_out, int out_size) {
    const float* vertices = (const float*)d_in[0];
    const float* uv_map   = (const float*)d_in[1];
    const int*   faces    = (const int*)d_in[2];
    const float* texture  = (const float*)d_in[3];
    const float* poses    = (const float*)d_in[4];
    float* out = (float*)d_out;

    int B = in_sizes[4] / 16;
    int N = in_sizes[0] / (3 * B);
    int F = in_sizes[2] / 3;
    long texel = (long)in_sizes[3] / (3L * B);
    int TH = (int)(sqrt((double)texel) + 0.5);
    int TW = TH;

    int npix = B * HW;
    k_init<<<(npix + 255) / 256, 256>>>(npix);
    k_transform<<<B, 256>>>(vertices, poses, N);
    int nwarps = B * F;
    k_raster<<<(nwarps * 32 + 255) / 256, 256>>>(faces, N, F, B);
    k_shade<<<(npix + 255) / 256, 256>>>(uv_map, faces, texture, out, N, F, TH, TW, B);
}

// round 5
// speedup vs baseline: 1.3821x; 1.3821x over previous
#include <cuda_runtime.h>
#include <cstdint>
#include <math.h>

#define IMG_H 128
#define IMG_W 128
#define HW (IMG_H * IMG_W)
#define B_MAX 4
#define N_MAX 4096
#define EPSF 1e-9f

typedef unsigned long long u64;
typedef unsigned int u32;

// Scratch (allocation-free: __device__ globals)
__device__ float4 g_verts[B_MAX * N_MAX];   // (sx, sy, sz, w) per vertex per batch
__device__ u64 g_zbuf[B_MAX * HW];          // (ordered_z << 32) | face_id

// ---------------------------------------------------------------------------
// Kernel 1: clear z-buffer
// ---------------------------------------------------------------------------
__global__ void k_init(int total) {
    int i = blockIdx.x * blockDim.x + threadIdx.x;
    if (i < total) g_zbuf[i] = 0xFFFFFFFFFFFFFFFFull;
}

// ---------------------------------------------------------------------------
// Kernel 2: vertex transform -> screen coords + clip w
// ---------------------------------------------------------------------------
__global__ void k_transform(const float* __restrict__ vertices,
                            const float* __restrict__ poses,
                            int N) {
    int b = blockIdx.x;
    const float* P = poses + b * 16;

    float C[4][4];
    const float sgn[3] = {1.f, -1.f, -1.f};
#pragma unroll
    for (int r = 0; r < 3; ++r)
#pragma unroll
        for (int c = 0; c < 3; ++c)
            C[r][c] = sgn[r] * P[r * 4 + c];
    C[0][3] = P[3];
    C[1][3] = -P[7];
    C[2][3] = -P[11];
#pragma unroll
    for (int c = 0; c < 4; ++c) C[3][c] = P[12 + c];

    const double NEAR = 0.1, FAR = 10.0, FOCAL = 140.0;
    const double RIGHT = (IMG_W - 1.0) / 2.0 * NEAR / FOCAL;
    const double TOP = RIGHT * ((double)IMG_H / (double)IMG_W);
    const float p00 = (float)(NEAR / RIGHT);
    const float p11 = (float)(NEAR / TOP);
    const float p22 = (float)(-(FAR + NEAR) / (FAR - NEAR));
    const float p32 = (float)(-2.0 * FAR * NEAR / (FAR - NEAR));

    const float* vb = vertices + (size_t)b * N * 3;
    for (int v = threadIdx.x; v < N; v += blockDim.x) {
        float x = vb[v * 3 + 0], y = vb[v * 3 + 1], z = vb[v * 3 + 2];
        float v0 = x * C[0][0] + y * C[0][1] + z * C[0][2] + C[0][3];
        float v1 = x * C[1][0] + y * C[1][1] + z * C[1][2] + C[1][3];
        float v2 = x * C[2][0] + y * C[2][1] + z * C[2][2] + C[2][3];
        float v3 = x * C[3][0] + y * C[3][1] + z * C[3][2] + C[3][3];
        float cx = v0 * p00;
        float cy = v1 * p11;
        float cz = v2 * p22 + v3 * p32;
        float cw = -v2;
        float sx = (cx / cw * 0.5f + 0.5f) * (float)IMG_W;
        float sy = (0.5f - cy / cw * 0.5f) * (float)IMG_H;
        float sz = cz / cw;
        g_verts[b * N + v] = make_float4(sx, sy, sz, cw);
    }
}

// ---------------------------------------------------------------------------
// Kernel 3: raster. 2 warps per face, flattened WIDENED bbox loop,
// PADDED early-Z, exact R1 numerics for edge/z tests.
// Key = (ordered_float(z) << 32) | face_id  -> lexicographic (z, fid) min.
// ---------------------------------------------------------------------------
#define SPLIT 2

__device__ __forceinline__ u32 ordf(float z) {
    u32 uz = __float_as_uint(z);
    return (uz & 0x80000000u) ? ~uz : (uz | 0x80000000u);
}

__global__ void k_raster(const int* __restrict__ faces, int N, int F, int B) {
    int gw = (blockIdx.x * blockDim.x + threadIdx.x) >> 5;
    int lane = threadIdx.x & 31;
    int fg = gw >> 1;           // face slot (b*F + f)
    int sub = gw & 1;
    if (fg >= B * F) return;
    int b = fg / F;
    int f = fg - b * F;

    int i0 = faces[3 * f + 0];
    int i1 = faces[3 * f + 1];
    int i2 = faces[3 * f + 2];
    float4 v0 = g_verts[b * N + i0];
    float4 v1 = g_verts[b * N + i1];
    float4 v2 = g_verts[b * N + i2];

    if (!(v0.w > 1e-6f && v1.w > 1e-6f && v2.w > 1e-6f)) return;

    float x0 = v0.x, y0 = v0.y, x1 = v1.x, y1 = v1.y, x2 = v2.x, y2 = v2.y;

    // WIDENED bbox (matches R1 passing kernel: absorbs fp rounding of edge fns)
    float minx = fminf(x0, fminf(x1, x2));
    float maxx = fmaxf(x0, fmaxf(x1, x2));
    float miny = fminf(y0, fminf(y1, y2));
    float maxy = fmaxf(y0, fmaxf(y1, y2));

    int c0 = max(0, (int)floorf(minx - 0.5f));
    int c1 = min(IMG_W - 1, (int)ceilf(maxx - 0.5f));
    int r0 = max(0, (int)floorf(miny - 0.5f));
    int r1 = min(IMG_H - 1, (int)ceilf(maxy - 0.5f));
    if (c1 < c0 || r1 < r0) return;

    float dx0 = x2 - x1, dy0 = y2 - y1;
    float dx1 = x0 - x2, dy1 = y0 - y2;
    float dx2 = x1 - x0, dy2 = y1 - y0;
    float z0 = v0.z, z1 = v1.z, z2 = v2.z;

    // Conservative PADDED face key: interpolated z >= min vertex z - 1e-5
    // (1e-5 abs margin >> worst-case convex-combination fp rounding ~1e-6)
    float zmn = fminf(z0, fminf(z1, z2)) - 1e-5f;
    if (zmn > 1.0f) return;
    u64 key_min = ((u64)ordf(zmn) << 32) | (u32)f;

    u32 W = (u32)(c1 - c0 + 1);
    u32 total = W * (u32)(r1 - r0 + 1);
    u32 m = 0xFFFFFFFFu / W + 1u;   // magic for i/W, i < 2^16

    u64* zb = g_zbuf + b * HW;
    u32 fid = (u32)f;

    for (u32 i = (u32)lane + 32u * (u32)sub; i < total; i += 32u * SPLIT) {
        u32 q = __umulhi(i, m);
        u32 cc = i - q * W;
        int r = r0 + (int)q;
        int c = c0 + (int)cc;
        u64* addr = zb + r * IMG_W + c;
        // Default (L1-cacheable) load: stale values are only LARGER
        // (buffer monotonically decreases), so the skip stays conservative.
        u64 cur = *addr;
        if (key_min >= cur) continue;

        float px = (float)c + 0.5f;
        float py = (float)r + 0.5f;
        // R1-identical numerics: unsigned edges, sign applied in the test
        float e0 = dx0 * (py - y1) - dy0 * (px - x1);
        float e1 = dx1 * (py - y2) - dy1 * (px - x2);
        float e2 = dx2 * (py - y0) - dy2 * (px - x0);
        float area = (e0 + e1) + e2;
        if (fabsf(area) <= EPSF) continue;
        float s = area > 0.f ? 1.f : -1.f;
        if (e0 * s < 0.f || e1 * s < 0.f || e2 * s < 0.f) continue;

        float num = e0 * z0 + e1 * z1;
        num += e2 * z2;
        float z = num / area;     // true division, matches reference rounding
        if (!(z >= -1.f && z <= 1.f)) continue;

        u64 key = ((u64)ordf(z) << 32) | fid;
        if (key < cur) atomicMin(addr, key);
    }
}

// ---------------------------------------------------------------------------
// Kernel 4: per-pixel perspective-correct shade + bilinear texture sample
// ---------------------------------------------------------------------------
__global__ void k_shade(const float* __restrict__ uv_map,
                        const int* __restrict__ faces,
                        const float* __restrict__ texture,
                        float* __restrict__ out,
                        int N, int F, int TH, int TW, int B) {
    int p = blockIdx.x * blockDim.x + threadIdx.x;
    if (p >= B * HW) return;
    int b = p / HW;
    int rc = p - b * HW;
    int r = rc / IMG_W;
    int c = rc - r * IMG_W;

    float o0 = 0.f, o1 = 0.f, o2 = 0.f;
    u64 key = g_zbuf[p];
    if (key != 0xFFFFFFFFFFFFFFFFull) {
        int f = (int)(u32)(key & 0xFFFFFFFFull);
        int i0 = faces[3 * f + 0];
        int i1 = faces[3 * f + 1];
        int i2 = faces[3 * f + 2];
        float4 v0 = g_verts[b * N + i0];
        float4 v1 = g_verts[b * N + i1];
        float4 v2 = g_verts[b * N + i2];

        float px = (float)c + 0.5f, py = (float)r + 0.5f;
        float e0 = (v2.x - v1.x) * (py - v1.y) - (v2.y - v1.y) * (px - v1.x);
        float e1 = (v0.x - v2.x) * (py - v2.y) - (v0.y - v2.y) * (px - v2.x);
        float e2 = (v1.x - v0.x) * (py - v0.y) - (v1.y - v0.y) * (px - v0.x);

        float bw0 = e0 / v0.w, bw1 = e1 / v1.w, bw2 = e2 / v2.w;
        float denom = (bw0 + bw1) + bw2;
        if (fabsf(denom) <= EPSF) denom = 1.f;
        float pc0 = bw0 / denom, pc1 = bw1 / denom, pc2 = bw2 / denom;

        float mask = (pc0 + pc1) + pc2;  // color channel 0 is all-ones

        const float* uvb = uv_map + (size_t)b * N * 2;
        float u = pc0 * __ldg(uvb + i0 * 2 + 0) + pc1 * __ldg(uvb + i1 * 2 + 0) + pc2 * __ldg(uvb + i2 * 2 + 0);
        float v = pc0 * __ldg(uvb + i0 * 2 + 1) + pc1 * __ldg(uvb + i1 * 2 + 1) + pc2 * __ldg(uvb + i2 * 2 + 1);

        float fyf = fminf(fmaxf(v, 0.f), 1.f) * (float)TH;
        float fxf = fminf(fmaxf(u, 0.f), 1.f) * (float)TW;
        float fly = floorf(fyf), flx = floorf(fxf);
        float fry = fyf - fly, frx = fxf - flx;
        int iy = (int)fly, ix = (int)flx;
        int iy0 = min(max(iy, 0), TH - 1);
        int iy1 = min(max(iy + 1, 0), TH - 1);
        int ix0 = min(max(ix, 0), TW - 1);
        int ix1 = min(max(ix + 1, 0), TW - 1);

        const float* T = texture + (size_t)b * TH * TW * 3;
        const float* tl = T + ((size_t)iy0 * TW + ix0) * 3;
        const float* tr = T + ((size_t)iy0 * TW + ix1) * 3;
        const float* bl = T + ((size_t)iy1 * TW + ix0) * 3;
        const float* br = T + ((size_t)iy1 * TW + ix1) * 3;

        float wtl = (1.f - frx) * (1.f - fry);
        float wtr = frx * (1.f - fry);
        float wbl = (1.f - frx) * fry;
        float wbr = frx * fry;

        o0 = (__ldg(tl + 0) * wtl + __ldg(tr + 0) * wtr + __ldg(bl + 0) * wbl + __ldg(br + 0) * wbr) * mask;
        o1 = (__ldg(tl + 1) * wtl + __ldg(tr + 1) * wtr + __ldg(bl + 1) * wbl + __ldg(br + 1) * wbr) * mask;
        o2 = (__ldg(tl + 2) * wtl + __ldg(tr + 2) * wtr + __ldg(bl + 2) * wbl + __ldg(br + 2) * wbr) * mask;
    }
    float* op = out + (size_t)p * 3;
    op[0] = o0;
    op[1] = o1;
    op[2] = o2;
}

// ---------------------------------------------------------------------------
// Launch
// ---------------------------------------------------------------------------
extern "C" void kernel_launch(void* const* d_in, const int* in_sizes, int n_in,
                              void* d_out, int out_size) {
    const float* vertices = (const float*)d_in[0];
    const float* uv_map   = (const float*)d_in[1];
    const int*   faces    = (const int*)d_in[2];
    const float* texture  = (const float*)d_in[3];
    const float* poses    = (const float*)d_in[4];
    float* out = (float*)d_out;

    int B = in_sizes[4] / 16;
    int N = in_sizes[0] / (3 * B);
    int F = in_sizes[2] / 3;
    long texel = (long)in_sizes[3] / (3L * B);
    int TH = (int)(sqrt((double)texel) + 0.5);
    int TW = TH;

    int npix = B * HW;
    k_init<<<(npix + 255) / 256, 256>>>(npix);
    k_transform<<<B, 256>>>(vertices, poses, N);
    int nwarps = B * F * SPLIT;
    k_raster<<<(nwarps * 32 + 255) / 256, 256>>>(faces, N, F, B);
    k_shade<<<(npix + 255) / 256, 256>>>(uv_map, faces, texture, out, N, F, TH, TW, B);
}

// round 8
// speedup vs baseline: 1.5513x; 1.1224x over previous
#include <cuda_runtime.h>
#include <cstdint>
#include <math.h>

#define IMG_H 128
#define IMG_W 128
#define HW (IMG_H * IMG_W)
#define B_MAX 4
#define F_MAX 8192
#define N_MAX 4096
#define EPSF 1e-9f
#define BINS 4096

typedef unsigned long long u64;
typedef unsigned int u32;

// Scratch (allocation-free: __device__ globals)
__device__ float4 g_verts[B_MAX * N_MAX];     // (sx, sy, sz, w)
__device__ u64 g_zbuf[B_MAX * HW];            // (ordered_z << 32) | face_id
__device__ u32 g_fz[B_MAX * F_MAX];           // per-(b,f) ordered-encoded zmin
__device__ u32 g_fbin[B_MAX * F_MAX];         // per-(b,f) depth bin
__device__ u32 g_sorted[B_MAX * F_MAX];       // (b*F+f) sorted front-to-back
__device__ u32 g_hist[BINS];
__device__ u32 g_cursor[BINS];
__device__ u32 g_zlo_u, g_zhi_u;              // ordered-encoded global zmin range

__device__ __forceinline__ u32 ordf(float z) {
    u32 uz = __float_as_uint(z);
    return (uz & 0x80000000u) ? ~uz : (uz | 0x80000000u);
}

// ---------------------------------------------------------------------------
// Kernel 1: clear z-buffer + histogram + range
// ---------------------------------------------------------------------------
__global__ void k_init(int npix) {
    int i = blockIdx.x * blockDim.x + threadIdx.x;
    if (i < npix) g_zbuf[i] = 0xFFFFFFFFFFFFFFFFull;
    else if (i < npix + BINS) g_hist[i - npix] = 0;
    if (i == 0) { g_zlo_u = 0xFFFFFFFFu; g_zhi_u = 0u; }
}

// ---------------------------------------------------------------------------
// Kernel 2: vertex transform -> screen coords + clip w
// ---------------------------------------------------------------------------
__global__ void k_transform(const float* __restrict__ vertices,
                            const float* __restrict__ poses,
                            int N) {
    int b = blockIdx.x;
    const float* P = poses + b * 16;

    float C[4][4];
    const float sgn[3] = {1.f, -1.f, -1.f};
#pragma unroll
    for (int r = 0; r < 3; ++r)
#pragma unroll
        for (int c = 0; c < 3; ++c)
            C[r][c] = sgn[r] * P[r * 4 + c];
    C[0][3] = P[3];
    C[1][3] = -P[7];
    C[2][3] = -P[11];
#pragma unroll
    for (int c = 0; c < 4; ++c) C[3][c] = P[12 + c];

    const double NEAR = 0.1, FAR = 10.0, FOCAL = 140.0;
    const double RIGHT = (IMG_W - 1.0) / 2.0 * NEAR / FOCAL;
    const double TOP = RIGHT * ((double)IMG_H / (double)IMG_W);
    const float p00 = (float)(NEAR / RIGHT);
    const float p11 = (float)(NEAR / TOP);
    const float p22 = (float)(-(FAR + NEAR) / (FAR - NEAR));
    const float p32 = (float)(-2.0 * FAR * NEAR / (FAR - NEAR));

    const float* vb = vertices + (size_t)b * N * 3;
    for (int v = threadIdx.x; v < N; v += blockDim.x) {
        float x = vb[v * 3 + 0], y = vb[v * 3 + 1], z = vb[v * 3 + 2];
        float v0 = x * C[0][0] + y * C[0][1] + z * C[0][2] + C[0][3];
        float v1 = x * C[1][0] + y * C[1][1] + z * C[1][2] + C[1][3];
        float v2 = x * C[2][0] + y * C[2][1] + z * C[2][2] + C[2][3];
        float v3 = x * C[3][0] + y * C[3][1] + z * C[3][2] + C[3][3];
        float cx = v0 * p00;
        float cy = v1 * p11;
        float cz = v2 * p22 + v3 * p32;
        float cw = -v2;
        float sx = (cx / cw * 0.5f + 0.5f) * (float)IMG_W;
        float sy = (0.5f - cy / cw * 0.5f) * (float)IMG_H;
        float sz = cz / cw;
        g_verts[b * N + v] = make_float4(sx, sy, sz, cw);
    }
}

// ---------------------------------------------------------------------------
// Kernel 3: per-face zmin (ordered-encoded) + global range
// ---------------------------------------------------------------------------
__global__ void k_facez(const int* __restrict__ faces, int N, int F, int B) {
    int idx = blockIdx.x * blockDim.x + threadIdx.x;
    if (idx >= B * F) return;
    int b = idx / F;
    int f = idx - b * F;
    int i0 = faces[3 * f + 0];
    int i1 = faces[3 * f + 1];
    int i2 = faces[3 * f + 2];
    float4 v0 = g_verts[b * N + i0];
    float4 v1 = g_verts[b * N + i1];
    float4 v2 = g_verts[b * N + i2];
    u32 e;
    if (v0.w > 1e-6f && v1.w > 1e-6f && v2.w > 1e-6f) {
        float zmn = fminf(v0.z, fminf(v1.z, v2.z));
        e = ordf(zmn);
        atomicMin(&g_zlo_u, e);
        atomicMax(&g_zhi_u, e);
    } else {
        e = 0xFFFFFFFFu;   // invalid -> last bin
    }
    g_fz[idx] = e;
}

// ---------------------------------------------------------------------------
// Kernel 4: histogram (bin in ordered-encoded space; monotone => order ok)
// ---------------------------------------------------------------------------
__global__ void k_hist(int F, int B) {
    int idx = blockIdx.x * blockDim.x + threadIdx.x;
    if (idx >= B * F) return;
    u32 e = g_fz[idx];
    u32 lo = g_zlo_u, hi = g_zhi_u;
    u32 bin;
    if (e == 0xFFFFFFFFu) bin = BINS - 1;
    else if (hi <= lo) bin = 0;
    else {
        u64 d = (u64)(e - lo);
        bin = (u32)((d * (u64)(BINS - 1)) / (u64)(hi - lo));
        if (bin > BINS - 2) bin = BINS - 2;
    }
    g_fbin[idx] = bin;
    atomicAdd(&g_hist[bin], 1u);
}

// ---------------------------------------------------------------------------
// Kernel 5: exclusive prefix sum over BINS (one block, 1024 threads x 4)
// ---------------------------------------------------------------------------
__global__ void k_scan() {
    __shared__ u32 a[1024];
    int t = threadIdx.x;
    u32 h[4], loc[4], s = 0;
#pragma unroll
    for (int j = 0; j < 4; ++j) {
        h[j] = g_hist[t * 4 + j];
        loc[j] = s;
        s += h[j];
    }
    a[t] = s;
    __syncthreads();
    for (int d = 1; d < 1024; d <<= 1) {
        u32 v = a[t];
        if (t >= d) v += a[t - d];
        __syncthreads();
        a[t] = v;
        __syncthreads();
    }
    u32 base = (t == 0) ? 0u : a[t - 1];
#pragma unroll
    for (int j = 0; j < 4; ++j)
        g_cursor[t * 4 + j] = base + loc[j];
}

// ---------------------------------------------------------------------------
// Kernel 6: scatter into sorted order
// ---------------------------------------------------------------------------
__global__ void k_scatter(int F, int B) {
    int idx = blockIdx.x * blockDim.x + threadIdx.x;
    if (idx >= B * F) return;
    u32 pos = atomicAdd(&g_cursor[g_fbin[idx]], 1u);
    g_sorted[pos] = (u32)idx;
}

// ---------------------------------------------------------------------------
// Kernel 7: raster, front-to-back order, 2 warps/face, 32-bit early-Z prune.
// Numerics identical to R5 passing kernel.
// ---------------------------------------------------------------------------
#define SPLIT 2

__global__ void k_raster(const int* __restrict__ faces, int N, int F, int B) {
    int gw = (blockIdx.x * blockDim.x + threadIdx.x) >> 5;
    int lane = threadIdx.x & 31;
    int slot = gw >> 1;
    int sub = gw & 1;
    if (slot >= B * F) return;
    int idx = (int)g_sorted[slot];
    int b = idx / F;
    int f = idx - b * F;

    int i0 = faces[3 * f + 0];
    int i1 = faces[3 * f + 1];
    int i2 = faces[3 * f + 2];
    float4 v0 = g_verts[b * N + i0];
    float4 v1 = g_verts[b * N + i1];
    float4 v2 = g_verts[b * N + i2];

    if (!(v0.w > 1e-6f && v1.w > 1e-6f && v2.w > 1e-6f)) return;

    float x0 = v0.x, y0 = v0.y, x1 = v1.x, y1 = v1.y, x2 = v2.x, y2 = v2.y;

    // Widened bbox (absorbs fp rounding of edge fns; matches passing kernel)
    float minx = fminf(x0, fminf(x1, x2));
    float maxx = fmaxf(x0, fmaxf(x1, x2));
    float miny = fminf(y0, fminf(y1, y2));
    float maxy = fmaxf(y0, fmaxf(y1, y2));

    int c0 = max(0, (int)floorf(minx - 0.5f));
    int c1 = min(IMG_W - 1, (int)ceilf(maxx - 0.5f));
    int r0 = max(0, (int)floorf(miny - 0.5f));
    int r1 = min(IMG_H - 1, (int)ceilf(maxy - 0.5f));
    if (c1 < c0 || r1 < r0) return;

    float dx0 = x2 - x1, dy0 = y2 - y1;
    float dx1 = x0 - x2, dy1 = y0 - y2;
    float dx2 = x1 - x0, dy2 = y1 - y0;
    float z0 = v0.z, z1 = v1.z, z2 = v2.z;

    // Conservative padded face z lower bound
    float zmn = fminf(z0, fminf(z1, z2)) - 1e-5f;
    if (zmn > 1.0f) return;
    u32 zmn_ord = ordf(zmn);

    u32 W = (u32)(c1 - c0 + 1);
    u32 total = W * (u32)(r1 - r0 + 1);
    u32 m = 0xFFFFFFFFu / W + 1u;   // magic for i/W, i < 2^16

    u64* zb = g_zbuf + b * HW;
    u32 fid = (u32)f;

    for (u32 i = (u32)lane + 32u * (u32)sub; i < total; i += 32u * SPLIT) {
        u32 q = __umulhi(i, m);
        u32 cc = i - q * W;
        int r = r0 + (int)q;
        int c = c0 + (int)cc;
        u64* addr = zb + r * IMG_W + c;
        // 32-bit prune on high word of key (stale L1 reads are only larger
        // since the buffer monotonically decreases -> conservative).
        u32 cur_hi = ((const u32*)addr)[1];
        if (zmn_ord > cur_hi) continue;

        float px = (float)c + 0.5f;
        float py = (float)r + 0.5f;
        float e0 = dx0 * (py - y1) - dy0 * (px - x1);
        float e1 = dx1 * (py - y2) - dy1 * (px - x2);
        float e2 = dx2 * (py - y0) - dy2 * (px - x0);
        float area = (e0 + e1) + e2;
        if (fabsf(area) <= EPSF) continue;
        float s = area > 0.f ? 1.f : -1.f;
        if (e0 * s < 0.f || e1 * s < 0.f || e2 * s < 0.f) continue;

        float num = e0 * z0 + e1 * z1;
        num += e2 * z2;
        float z = num / area;     // exact division: matches reference rounding
        if (!(z >= -1.f && z <= 1.f)) continue;

        u32 uz = ordf(z);
        if (uz > cur_hi) continue;   // conservative: stale cur_hi >= actual
        u64 key = ((u64)uz << 32) | fid;
        atomicMin(addr, key);
    }
}

// ---------------------------------------------------------------------------
// Kernel 8: per-pixel perspective-correct shade + bilinear texture sample
// ---------------------------------------------------------------------------
__global__ void k_shade(const float* __restrict__ uv_map,
                        const int* __restrict__ faces,
                        const float* __restrict__ texture,
                        float* __restrict__ out,
                        int N, int F, int TH, int TW, int B) {
    int p = blockIdx.x * blockDim.x + threadIdx.x;
    if (p >= B * HW) return;
    int b = p / HW;
    int rc = p - b * HW;
    int r = rc / IMG_W;
    int c = rc - r * IMG_W;

    float o0 = 0.f, o1 = 0.f, o2 = 0.f;
    u64 key = g_zbuf[p];
    if (key != 0xFFFFFFFFFFFFFFFFull) {
        int f = (int)(u32)(key & 0xFFFFFFFFull);
        int i0 = faces[3 * f + 0];
        int i1 = faces[3 * f + 1];
        int i2 = faces[3 * f + 2];
        float4 v0 = g_verts[b * N + i0];
        float4 v1 = g_verts[b * N + i1];
        float4 v2 = g_verts[b * N + i2];

        float px = (float)c + 0.5f, py = (float)r + 0.5f;
        float e0 = (v2.x - v1.x) * (py - v1.y) - (v2.y - v1.y) * (px - v1.x);
        float e1 = (v0.x - v2.x) * (py - v2.y) - (v0.y - v2.y) * (px - v2.x);
        float e2 = (v1.x - v0.x) * (py - v0.y) - (v1.y - v0.y) * (px - v0.x);

        float bw0 = e0 / v0.w, bw1 = e1 / v1.w, bw2 = e2 / v2.w;
        float denom = (bw0 + bw1) + bw2;
        if (fabsf(denom) <= EPSF) denom = 1.f;
        float pc0 = bw0 / denom, pc1 = bw1 / denom, pc2 = bw2 / denom;

        float mask = (pc0 + pc1) + pc2;  // color channel 0 is all-ones

        const float* uvb = uv_map + (size_t)b * N * 2;
        float u = pc0 * __ldg(uvb + i0 * 2 + 0) + pc1 * __ldg(uvb + i1 * 2 + 0) + pc2 * __ldg(uvb + i2 * 2 + 0);
        float v = pc0 * __ldg(uvb + i0 * 2 + 1) + pc1 * __ldg(uvb + i1 * 2 + 1) + pc2 * __ldg(uvb + i2 * 2 + 1);

        float fyf = fminf(fmaxf(v, 0.f), 1.f) * (float)TH;
        float fxf = fminf(fmaxf(u, 0.f), 1.f) * (float)TW;
        float fly = floorf(fyf), flx = floorf(fxf);
        float fry = fyf - fly, frx = fxf - flx;
        int iy = (int)fly, ix = (int)flx;
        int iy0 = min(max(iy, 0), TH - 1);
        int iy1 = min(max(iy + 1, 0), TH - 1);
        int ix0 = min(max(ix, 0), TW - 1);
        int ix1 = min(max(ix + 1, 0), TW - 1);

        const float* T = texture + (size_t)b * TH * TW * 3;
        const float* tl = T + ((size_t)iy0 * TW + ix0) * 3;
        const float* tr = T + ((size_t)iy0 * TW + ix1) * 3;
        const float* bl = T + ((size_t)iy1 * TW + ix0) * 3;
        const float* br = T + ((size_t)iy1 * TW + ix1) * 3;

        float wtl = (1.f - frx) * (1.f - fry);
        float wtr = frx * (1.f - fry);
        float wbl = (1.f - frx) * fry;
        float wbr = frx * fry;

        o0 = (__ldg(tl + 0) * wtl + __ldg(tr + 0) * wtr + __ldg(bl + 0) * wbl + __ldg(br + 0) * wbr) * mask;
        o1 = (__ldg(tl + 1) * wtl + __ldg(tr + 1) * wtr + __ldg(bl + 1) * wbl + __ldg(br + 1) * wbr) * mask;
        o2 = (__ldg(tl + 2) * wtl + __ldg(tr + 2) * wtr + __ldg(bl + 2) * wbl + __ldg(br + 2) * wbr) * mask;
    }
    float* op = out + (size_t)p * 3;
    op[0] = o0;
    op[1] = o1;
    op[2] = o2;
}

// ---------------------------------------------------------------------------
// Launch
// ---------------------------------------------------------------------------
extern "C" void kernel_launch(void* const* d_in, const int* in_sizes, int n_in,
                              void* d_out, int out_size) {
    const float* vertices = (const float*)d_in[0];
    const float* uv_map   = (const float*)d_in[1];
    const int*   faces    = (const int*)d_in[2];
    const float* texture  = (const float*)d_in[3];
    const float* poses    = (const float*)d_in[4];
    float* out = (float*)d_out;

    int B = in_sizes[4] / 16;
    int N = in_sizes[0] / (3 * B);
    int F = in_sizes[2] / 3;
    long texel = (long)in_sizes[3] / (3L * B);
    int TH = (int)(sqrt((double)texel) + 0.5);
    int TW = TH;

    int npix = B * HW;
    int nf = B * F;
    k_init<<<(npix + BINS + 255) / 256, 256>>>(npix);
    k_transform<<<B, 256>>>(vertices, poses, N);
    k_facez<<<(nf + 255) / 256, 256>>>(faces, N, F, B);
    k_hist<<<(nf + 255) / 256, 256>>>(F, B);
    k_scan<<<1, 1024>>>();
    k_scatter<<<(nf + 255) / 256, 256>>>(F, B);
    int nwarps = nf * SPLIT;
    k_raster<<<(nwarps * 32 + 255) / 256, 256>>>(faces, N, F, B);
    k_shade<<<(npix + 255) / 256, 256>>>(uv_map, faces, texture, out, N, F, TH, TW, B);
}